// round 6
// baseline (speedup 1.0000x reference)
#include <cuda_runtime.h>

// Depthwise 3x3 lateral conv (center tap excluded) + residual, NHWC f32.
// x: [32,56,56,256], kernel: [3,3,256], out: [32,56,56,256]
//
// R6: scalar-float granularity for max occupancy. Thread owns 1 channel;
// 256-thread block covers all channels; HR=2 x WR=4 spatial tile per thread.
// ~40 regs -> 48 warps/SM (75% occ) vs 32 warps at float2 (reg-file capped).
// Interior blocks (~80%) take the branch-free fast path: 24 loads off one
// base pointer with immediate offsets. Taps in registers; residual folded
// as a center-pixel add.

#define H 56
#define W 56
#define C 256
#define HR 2
#define WR 4

__global__ __launch_bounds__(256, 6) void contour_kernel(
    const float* __restrict__ x,
    const float* __restrict__ kern,
    float* __restrict__ out)
{
    const int c  = threadIdx.x;              // 0..255 (one channel)
    const int wb = blockIdx.x * WR;          // 0,4,...,52
    const int hb = blockIdx.y * HR;          // 0,2,...,54
    const int b  = blockIdx.z;

    // 8 lateral taps -> registers (center excluded; handled as residual add)
    float kreg[8];
    #pragma unroll
    for (int t = 0; t < 8; t++) {
        const int tap = t + (t >= 4 ? 1 : 0);
        kreg[t] = kern[tap * C + c];
    }

    const int img = b * (H * W * C);         // max ~25.7M, fits int32

    float acc[HR][WR];
    #pragma unroll
    for (int r = 0; r < HR; r++)
        #pragma unroll
        for (int j = 0; j < WR; j++)
            acc[r][j] = 0.f;

    const bool interior = (hb >= 1) & (hb + HR + 1 <= H) & (wb >= 1) & (wb + WR + 1 <= W);

    if (interior) {
        const float* __restrict__ p = x + img + ((hb - 1) * W + (wb - 1)) * C + c;

        #pragma unroll
        for (int ih = 0; ih < HR + 2; ih++) {
            float v[WR + 2];
            #pragma unroll
            for (int j = 0; j < WR + 2; j++)
                v[j] = p[(ih * W + j) * C];

            #pragma unroll
            for (int r = 0; r < HR; r++) {
                const int kh = ih - r;
                if (kh < 0 || kh > 2) continue;
                #pragma unroll
                for (int dw = 0; dw < 3; dw++) {
                    const bool is_center = (kh == 1 && dw == 1);
                    const int lin = kh * 3 + dw;
                    const int t = lin - (lin > 4 ? 1 : 0);
                    #pragma unroll
                    for (int j = 0; j < WR; j++) {
                        if (is_center) acc[r][j] += v[j + 1];          // residual
                        else           acc[r][j] = fmaf(v[j + dw], kreg[t], acc[r][j]);
                    }
                }
            }
        }
    } else {
        #pragma unroll
        for (int ih = 0; ih < HR + 2; ih++) {
            const int row = hb - 1 + ih;
            if (row < 0 || row >= H) continue;
            const int rb = img + row * (W * C) + c;

            float v[WR + 2];
            #pragma unroll
            for (int j = 0; j < WR + 2; j++) {
                const int col = wb - 1 + j;
                v[j] = ((unsigned)col < (unsigned)W) ? x[rb + col * C] : 0.f;
            }

            #pragma unroll
            for (int r = 0; r < HR; r++) {
                const int kh = ih - r;
                if (kh < 0 || kh > 2) continue;
                #pragma unroll
                for (int dw = 0; dw < 3; dw++) {
                    const bool is_center = (kh == 1 && dw == 1);
                    const int lin = kh * 3 + dw;
                    const int t = lin - (lin > 4 ? 1 : 0);
                    #pragma unroll
                    for (int j = 0; j < WR; j++) {
                        if (is_center) acc[r][j] += v[j + 1];
                        else           acc[r][j] = fmaf(v[j + dw], kreg[t], acc[r][j]);
                    }
                }
            }
        }
    }

    #pragma unroll
    for (int r = 0; r < HR; r++) {
        const int rb = img + (hb + r) * (W * C) + c;
        #pragma unroll
        for (int j = 0; j < WR; j++)
            out[rb + (wb + j) * C] = acc[r][j];
    }
}

extern "C" void kernel_launch(void* const* d_in, const int* in_sizes, int n_in,
                              void* d_out, int out_size)
{
    const float* x    = (const float*)d_in[0];   // [32,56,56,256]
    const float* kern = (const float*)d_in[1];   // [3,3,256]
    float* outp       = (float*)d_out;

    dim3 block(C, 1, 1);             // 256 threads: one channel each
    dim3 grid(W / WR, H / HR, 32);   // 14 x 28 x 32 = 12544 blocks
    contour_kernel<<<grid, block>>>(x, kern, outp);
}

// round 7
// speedup vs baseline: 1.1234x; 1.1234x over previous
#include <cuda_runtime.h>

// Depthwise 3x3 lateral conv (center tap excluded) + residual, NHWC f32.
// x: [32,56,56,256], kernel: [3,3,256], out: [32,56,56,256]
//
// R7: float2 granularity, HR=2 x WR=4 tile, interior fast path now
// FRONT-BATCHES all 24 loads into a live v[4][6] register array before any
// FMA, so the full tile's memory latency is covered by one MLP batch
// (24 x 256B = 6KB in flight per warp). __launch_bounds__(128,5) gives the
// ~95 regs this needs. R5 lesson: 64 regs forced 4 serial batches of 6.
// R6 lesson: occupancy alone does not add bytes-in-flight.

#define H 56
#define W 56
#define C2 128        // channels as float2
#define HR 2
#define WR 4

__device__ __forceinline__ void f2fma(float2& a, float2 v, float2 k) {
    a.x = fmaf(v.x, k.x, a.x);
    a.y = fmaf(v.y, k.y, a.y);
}

__global__ __launch_bounds__(128, 5) void contour_kernel(
    const float* __restrict__ x,
    const float* __restrict__ kern,
    float* __restrict__ out)
{
    const int c2 = threadIdx.x;              // 0..127 (2 channels)
    const int wb = blockIdx.x * WR;          // 0,4,...,52
    const int hb = blockIdx.y * HR;          // 0,2,...,54
    const int b  = blockIdx.z;

    const float2* __restrict__ xin = reinterpret_cast<const float2*>(x);
    const float2* __restrict__ k2  = reinterpret_cast<const float2*>(kern);
    float2* __restrict__ o = reinterpret_cast<float2*>(out);

    // 8 lateral taps -> registers (center excluded; residual = center add)
    float2 kreg[8];
    #pragma unroll
    for (int t = 0; t < 8; t++) {
        const int tap = t + (t >= 4 ? 1 : 0);
        kreg[t] = k2[tap * C2 + c2];
    }

    const int img = b * (H * W * C2);

    float2 acc[HR][WR];
    #pragma unroll
    for (int r = 0; r < HR; r++)
        #pragma unroll
        for (int j = 0; j < WR; j++)
            acc[r][j] = make_float2(0.f, 0.f);

    const bool interior = (hb >= 1) & (hb + HR + 1 <= H) & (wb >= 1) & (wb + WR + 1 <= W);

    if (interior) {
        const float2* __restrict__ p =
            xin + img + ((hb - 1) * W + (wb - 1)) * C2 + c2;

        // ---- front-batch ALL tile loads: 4 rows x 6 cols live at once ----
        float2 v[HR + 2][WR + 2];
        #pragma unroll
        for (int ih = 0; ih < HR + 2; ih++)
            #pragma unroll
            for (int j = 0; j < WR + 2; j++)
                v[ih][j] = p[(ih * W + j) * C2];

        // ---- compute ----
        #pragma unroll
        for (int ih = 0; ih < HR + 2; ih++) {
            #pragma unroll
            for (int r = 0; r < HR; r++) {
                const int kh = ih - r;
                if (kh < 0 || kh > 2) continue;
                #pragma unroll
                for (int dw = 0; dw < 3; dw++) {
                    const bool is_center = (kh == 1 && dw == 1);
                    const int lin = kh * 3 + dw;
                    const int t = lin - (lin > 4 ? 1 : 0);
                    #pragma unroll
                    for (int j = 0; j < WR; j++) {
                        if (is_center) {
                            acc[r][j].x += v[ih][j + 1].x;   // residual
                            acc[r][j].y += v[ih][j + 1].y;
                        } else {
                            f2fma(acc[r][j], v[ih][j + dw], kreg[t]);
                        }
                    }
                }
            }
        }
    } else {
        #pragma unroll
        for (int ih = 0; ih < HR + 2; ih++) {
            const int row = hb - 1 + ih;
            if (row < 0 || row >= H) continue;
            const int rb = img + row * (W * C2) + c2;

            float2 v[WR + 2];
            #pragma unroll
            for (int j = 0; j < WR + 2; j++) {
                const int col = wb - 1 + j;
                v[j] = ((unsigned)col < (unsigned)W) ? xin[rb + col * C2]
                                                     : make_float2(0.f, 0.f);
            }

            #pragma unroll
            for (int r = 0; r < HR; r++) {
                const int kh = ih - r;
                if (kh < 0 || kh > 2) continue;
                #pragma unroll
                for (int dw = 0; dw < 3; dw++) {
                    const bool is_center = (kh == 1 && dw == 1);
                    const int lin = kh * 3 + dw;
                    const int t = lin - (lin > 4 ? 1 : 0);
                    #pragma unroll
                    for (int j = 0; j < WR; j++) {
                        if (is_center) {
                            acc[r][j].x += v[j + 1].x;
                            acc[r][j].y += v[j + 1].y;
                        } else {
                            f2fma(acc[r][j], v[j + dw], kreg[t]);
                        }
                    }
                }
            }
        }
    }

    #pragma unroll
    for (int r = 0; r < HR; r++) {
        const int rb = img + (hb + r) * (W * C2) + c2;
        #pragma unroll
        for (int j = 0; j < WR; j++)
            o[rb + (wb + j) * C2] = acc[r][j];
    }
}

extern "C" void kernel_launch(void* const* d_in, const int* in_sizes, int n_in,
                              void* d_out, int out_size)
{
    const float* x    = (const float*)d_in[0];   // [32,56,56,256]
    const float* kern = (const float*)d_in[1];   // [3,3,256]
    float* outp       = (float*)d_out;

    dim3 block(C2, 1, 1);            // 128 threads
    dim3 grid(W / WR, H / HR, 32);   // 14 x 28 x 32 = 12544 blocks
    contour_kernel<<<grid, block>>>(x, kern, outp);
}